// round 8
// baseline (speedup 1.0000x reference)
#include <cuda_runtime.h>
#include <cuda_bf16.h>
#include <cstdint>

// Output: [32, 4096, 1024] fp32. out[..., c] = coef if (c odd && c < 1022) else 0.
// Row = 1024 floats = 256 float4s; all float4s are (0,coef,0,coef) except the
// last float4 of each row which is (0,coef,0,0).
//
// Single-wave contiguous layout: 1024 blocks x 256 threads, each block owns a
// contiguous 32768-float4 (512KB) span; each thread stores 128 float4s at
// offsets k*4096B (max 508KB -> fits STG immediate field -> one base pointer,
// low regs, full unroll). 1024 blocks <= 1184 resident slots = ONE wave, no
// wave transitions. Block base is a multiple of 256 vec4s, so every store by
// thread t lands at within-row float4 index t: only tid==255 writes row-tail
// float4s and the store value is a per-thread constant.

static constexpr long long TOTAL_VEC4     = 32LL * 4096LL * 1024LL / 4;  // 33,554,432
static constexpr int       THREADS        = 256;
static constexpr int       BLOCKS         = 1024;                         // single wave
static constexpr int       VEC_PER_THREAD = (int)(TOTAL_VEC4 / ((long long)BLOCKS * THREADS)); // 128
static constexpr int       VEC_PER_BLOCK  = THREADS * VEC_PER_THREAD;     // 32768

__global__ __launch_bounds__(THREADS)
void posenc_fill_kernel(float4* __restrict__ out,
                        const float* __restrict__ coef_ptr) {
    const float coef = __ldg(coef_ptr);
    const float w3 = (threadIdx.x == THREADS - 1) ? 0.0f : coef;
    const float4 val = make_float4(0.0f, coef, 0.0f, w3);

    float4* p = out + (long long)blockIdx.x * VEC_PER_BLOCK + threadIdx.x;
#pragma unroll
    for (int k = 0; k < VEC_PER_THREAD; ++k) {
        p[k * THREADS] = val;   // STG.E.128 [Rbase + k*4096]
    }
}

extern "C" void kernel_launch(void* const* d_in, const int* in_sizes, int n_in,
                              void* d_out, int out_size) {
    const float* coef = (const float*)d_in[n_in - 1];  // coef_param is last input
    posenc_fill_kernel<<<BLOCKS, THREADS>>>((float4*)d_out, coef);
}

// round 9
// speedup vs baseline: 1.1718x; 1.1718x over previous
#include <cuda_runtime.h>
#include <cuda_bf16.h>
#include <cstdint>

// Output: [32, 4096, 1024] fp32. out[..., c] = coef if (c odd && c < 1022) else 0.
// Row = 1024 floats = 256 float4s; all float4s are (0,coef,0,coef) except the
// last float4 of each row which is (0,coef,0,0).
//
// Granularity probe: 16384 blocks x 256 threads, 8 float4 stores per thread
// at stride 256 float4s (immediate offsets 0..28KB). Finer blocks than the
// 77.8us round-2 config (8192x16) to shrink the end-of-kernel drain tail —
// round 8 showed big blocks (1024x128) cost 12us in straggler drain, so the
// balance axis points toward finer granularity, bounded below by ALU cost
// (round 1: grid-stride per-element logic was ALU-bound at 109us).
// VEC_PER_BLOCK = 2048, a multiple of 256, so every store by thread t lands
// at within-row float4 index t: only tid==255 writes row-tail float4s and
// the store value is a per-thread constant.

static constexpr long long TOTAL_VEC4     = 32LL * 4096LL * 1024LL / 4;  // 33,554,432
static constexpr int       THREADS        = 256;
static constexpr int       VEC_PER_THREAD = 8;
static constexpr int       VEC_PER_BLOCK  = THREADS * VEC_PER_THREAD;    // 2048
static constexpr int       BLOCKS         = (int)(TOTAL_VEC4 / VEC_PER_BLOCK); // 16384

__global__ __launch_bounds__(THREADS)
void posenc_fill_kernel(float4* __restrict__ out,
                        const float* __restrict__ coef_ptr) {
    const float coef = __ldg(coef_ptr);
    const float w3 = (threadIdx.x == THREADS - 1) ? 0.0f : coef;
    const float4 val = make_float4(0.0f, coef, 0.0f, w3);

    float4* p = out + (long long)blockIdx.x * VEC_PER_BLOCK + threadIdx.x;
#pragma unroll
    for (int k = 0; k < VEC_PER_THREAD; ++k) {
        p[k * THREADS] = val;   // STG.E.128 [Rbase + k*4096]
    }
}

extern "C" void kernel_launch(void* const* d_in, const int* in_sizes, int n_in,
                              void* d_out, int out_size) {
    const float* coef = (const float*)d_in[n_in - 1];  // coef_param is last input
    posenc_fill_kernel<<<BLOCKS, THREADS>>>((float4*)d_out, coef);
}

// round 10
// speedup vs baseline: 1.1896x; 1.0152x over previous
#include <cuda_runtime.h>
#include <cuda_bf16.h>
#include <cstdint>

// Output: [32, 4096, 1024] fp32. out[..., c] = coef if (c odd && c < 1022) else 0.
// Row = 1024 floats = 256 float4s; all float4s are (0,coef,0,coef) except the
// last float4 of each row which is (0,coef,0,0).
//
// Granularity probe, one step finer than round 9's winner (16384x8 = 73.9us,
// DRAM 79.2%): 32768 blocks x 256 threads, 4 float4 stores per thread at
// stride 256 float4s (immediate offsets 0..12KB). Granularity scan so far:
//   1024x128 -> 85.8us (drain-tail bound)
//   8192x16  -> 76.3us
//   16384x8  -> 73.9us (issue only 6.8%)
//   per-elem -> ALU-bound (109us)
// VEC_PER_BLOCK = 1024, a multiple of 256, so every store by thread t lands
// at within-row float4 index t: only tid==255 writes row-tail float4s and
// the store value is a per-thread constant.

static constexpr long long TOTAL_VEC4     = 32LL * 4096LL * 1024LL / 4;  // 33,554,432
static constexpr int       THREADS        = 256;
static constexpr int       VEC_PER_THREAD = 4;
static constexpr int       VEC_PER_BLOCK  = THREADS * VEC_PER_THREAD;    // 1024
static constexpr int       BLOCKS         = (int)(TOTAL_VEC4 / VEC_PER_BLOCK); // 32768

__global__ __launch_bounds__(THREADS)
void posenc_fill_kernel(float4* __restrict__ out,
                        const float* __restrict__ coef_ptr) {
    const float coef = __ldg(coef_ptr);
    const float w3 = (threadIdx.x == THREADS - 1) ? 0.0f : coef;
    const float4 val = make_float4(0.0f, coef, 0.0f, w3);

    float4* p = out + (long long)blockIdx.x * VEC_PER_BLOCK + threadIdx.x;
#pragma unroll
    for (int k = 0; k < VEC_PER_THREAD; ++k) {
        p[k * THREADS] = val;   // STG.E.128 [Rbase + k*4096]
    }
}

extern "C" void kernel_launch(void* const* d_in, const int* in_sizes, int n_in,
                              void* d_out, int out_size) {
    const float* coef = (const float*)d_in[n_in - 1];  // coef_param is last input
    posenc_fill_kernel<<<BLOCKS, THREADS>>>((float4*)d_out, coef);
}